// round 6
// baseline (speedup 1.0000x reference)
#include <cuda_runtime.h>
#include <cuda_bf16.h>

#define N_NODES 100000
#define N_EDGES 1600000
#define F_IN 128
#define F_OUT 64
#define BN_EPS 1e-5f

#define NB 148            // persistent blocks (<= SM count, co-resident)
#define NT 1024
#define NTHREADS (NB*NT)
#define NODES_PER_BLK 676 // 148*676 = 100048 >= N_NODES
#define TILE_NODES 256
#define N_TILES 391       // ceil(100000/256)
#define KC 32             // k-chunk
#define SX_STRIDE 36      // pad: conflict-free + float4-aligned

// ---------------- device scratch ----------------
__device__ __align__(16) float g_h[N_NODES * F_OUT];
__device__ __align__(16) float g_Wt[F_IN * F_OUT];    // transposed W: [k][o]
__device__ __align__(16) float g_dinv[N_NODES];
__device__ int   g_deg[N_NODES];
__device__ int   g_cnt[N_NODES];
__device__ int   g_rowptr[N_NODES + 1];
__device__ int   g_cursor[N_NODES];
__device__ __align__(16) unsigned long long g_edge[N_EDGES];
__device__ int   g_bsum[NB];
__device__ float g_sum[F_OUT];
__device__ float g_sumsq[F_OUT];

struct Bar { int cnt; int flag; };
__device__ Bar g_bars[8];   // zero-init; self-resetting across replays

__device__ __forceinline__ void grid_sync(int i) {
    __syncthreads();
    if (threadIdx.x == 0) {
        Bar* b = &g_bars[i];
        // flag is stable here: it can only advance after *all* blocks
        // (including this one) arrive, and we haven't arrived yet.
        int snap = atomicAdd(&b->flag, 0);
        __threadfence();
        int old = atomicAdd(&b->cnt, 1);
        if (old == NB - 1) {
            atomicExch(&b->cnt, 0);        // reset for next graph replay
            __threadfence();
            atomicAdd(&b->flag, 1);        // release
        } else {
            while (atomicAdd(&b->flag, 0) == snap) __nanosleep(64);
        }
        __threadfence();
    }
    __syncthreads();
}

union SMemU {
    struct { float sW[KC * F_OUT]; float sX[TILE_NODES * SX_STRIDE]; } g;  // 8KB + 36KB
    int scan[NT];
    struct { float psum[32][F_OUT]; float psq[32][F_OUT]; } agg;           // 32KB
    struct { float scale[F_OUT]; float shift[F_OUT]; } bn;
};

__global__ __launch_bounds__(NT, 1)
void k_mega(const float* __restrict__ x, const int* __restrict__ ei,
            const float* __restrict__ ew, const float* __restrict__ W,
            const float* __restrict__ gamma, const float* __restrict__ beta,
            float* __restrict__ out) {
    __shared__ SMemU sm;
    __shared__ int s_base;
    int tid = threadIdx.x;
    int bid = blockIdx.x;
    int gtid = bid * NT + tid;

    // ---------- Phase A: init ----------
    for (int i = gtid; i < N_NODES; i += NTHREADS) { g_deg[i] = 1; g_cnt[i] = 0; }
    for (int i = gtid; i < F_IN * F_OUT; i += NTHREADS) {
        int k = i >> 6, o = i & 63;
        g_Wt[i] = W[o * F_IN + k];
    }
    if (gtid < F_OUT) { g_sum[gtid] = 0.f; g_sumsq[gtid] = 0.f; }
    if (gtid == 0) g_rowptr[N_NODES] = N_EDGES;
    grid_sync(0);

    // ---------- Phase B: degree + dst histogram ----------
    for (int e = gtid; e < N_EDGES; e += NTHREADS) {
        int s = ei[e];
        int d = ei[N_EDGES + e];
        atomicAdd(&g_deg[s], 1);
        atomicAdd(&g_cnt[d], 1);
    }
    grid_sync(1);

    // ---------- Phase C: dinv + hierarchical exclusive scan ----------
    int node = bid * NODES_PER_BLK + tid;
    int v = 0;
    if (tid < NODES_PER_BLK && node < N_NODES) {
        g_dinv[node] = rsqrtf((float)g_deg[node]);
        v = g_cnt[node];
    }
    sm.scan[tid] = v;
    __syncthreads();
    for (int off = 1; off < NT; off <<= 1) {
        int t = (tid >= off) ? sm.scan[tid - off] : 0;
        __syncthreads();
        sm.scan[tid] += t;
        __syncthreads();
    }
    int incl = sm.scan[tid];
    if (tid == NT - 1) g_bsum[bid] = incl;
    grid_sync(2);
    if (tid < 32) {
        int acc = 0;
        for (int j = tid; j < bid; j += 32) acc += g_bsum[j];
        #pragma unroll
        for (int off = 16; off > 0; off >>= 1)
            acc += __shfl_xor_sync(0xffffffffu, acc, off);
        if (tid == 0) s_base = acc;
    }
    __syncthreads();
    if (tid < NODES_PER_BLK && node < N_NODES) {
        int excl = s_base + incl - v;
        g_rowptr[node] = excl;
        g_cursor[node] = excl;
    }
    grid_sync(3);

    // ---------- Phase D: scatter edges into CSR ----------
    for (int e = gtid; e < N_EDGES; e += NTHREADS) {
        int s = ei[e];
        int d = ei[N_EDGES + e];
        float c = g_dinv[s] * ew[e] * g_dinv[d];
        int p = atomicAdd(&g_cursor[d], 1);
        g_edge[p] = ((unsigned long long)__float_as_uint(c) << 32) | (unsigned)s;
    }

    // ---------- Phase E: GEMM h = x @ W^T (no barrier needed before) ----------
    {
        int og = tid & 15;   // 16 out-groups x 4 outs
        int ng = tid >> 4;   // 64 node-groups x 4 nodes
        for (int tile = bid; tile < N_TILES; tile += NB) {
            int nbase = tile * TILE_NODES;
            unsigned long long acc[4][2];
            #pragma unroll
            for (int a = 0; a < 4; a++) { acc[a][0] = 0ull; acc[a][1] = 0ull; }

            for (int kc = 0; kc < F_IN; kc += KC) {
                __syncthreads();
                // fill sW chunk [KC][64] from transposed W (coalesced)
                for (int i = tid; i < KC * F_OUT / 4; i += NT)
                    ((float4*)sm.g.sW)[i] = ((const float4*)(g_Wt + kc * F_OUT))[i];
                // fill sX chunk [256 nodes][KC]
                for (int i = tid; i < TILE_NODES * KC / 4; i += NT) {
                    int n = i >> 3, kq = i & 7;
                    int gn = nbase + n;
                    float4 val = make_float4(0.f, 0.f, 0.f, 0.f);
                    if (gn < N_NODES)
                        val = *(const float4*)(x + (size_t)gn * F_IN + kc + kq * 4);
                    *(float4*)&sm.g.sX[n * SX_STRIDE + kq * 4] = val;
                }
                __syncthreads();

                #pragma unroll 4
                for (int kp = 0; kp < KC; kp += 2) {
                    ulonglong2 wA = *(const ulonglong2*)&sm.g.sW[kp * F_OUT + og * 4];
                    ulonglong2 wB = *(const ulonglong2*)&sm.g.sW[(kp + 1) * F_OUT + og * 4];
                    #pragma unroll
                    for (int ni = 0; ni < 4; ni++) {
                        float2 xv = *(const float2*)&sm.g.sX[(ng * 4 + ni) * SX_STRIDE + kp];
                        unsigned long long x0d, x1d;
                        unsigned x0 = __float_as_uint(xv.x);
                        unsigned x1 = __float_as_uint(xv.y);
                        asm("mov.b64 %0, {%1, %1};" : "=l"(x0d) : "r"(x0));
                        asm("mov.b64 %0, {%1, %1};" : "=l"(x1d) : "r"(x1));
                        asm("fma.rn.f32x2 %0, %1, %2, %0;" : "+l"(acc[ni][0]) : "l"(wA.x), "l"(x0d));
                        asm("fma.rn.f32x2 %0, %1, %2, %0;" : "+l"(acc[ni][1]) : "l"(wA.y), "l"(x0d));
                        asm("fma.rn.f32x2 %0, %1, %2, %0;" : "+l"(acc[ni][0]) : "l"(wB.x), "l"(x1d));
                        asm("fma.rn.f32x2 %0, %1, %2, %0;" : "+l"(acc[ni][1]) : "l"(wB.y), "l"(x1d));
                    }
                }
            }
            #pragma unroll
            for (int ni = 0; ni < 4; ni++) {
                int n = nbase + ng * 4 + ni;
                if (n < N_NODES) {
                    unsigned a0, a1, a2, a3;
                    asm("mov.b64 {%0, %1}, %2;" : "=r"(a0), "=r"(a1) : "l"(acc[ni][0]));
                    asm("mov.b64 {%0, %1}, %2;" : "=r"(a2), "=r"(a3) : "l"(acc[ni][1]));
                    *(float4*)&g_h[(size_t)n * F_OUT + og * 4] =
                        make_float4(__uint_as_float(a0), __uint_as_float(a1),
                                    __uint_as_float(a2), __uint_as_float(a3));
                }
            }
        }
    }
    grid_sync(4);   // covers scatter (D) and gemm (E)

    // ---------- Phase F: aggregation (warp per node) + BN partial sums ----------
    {
        int warp = tid >> 5, lane = tid & 31;
        int gw = bid * 32 + warp;
        float s0 = 0.f, s1 = 0.f, q0 = 0.f, q1 = 0.f;
        const float2* h2 = (const float2*)g_h;
        for (int n = gw; n < N_NODES; n += NB * 32) {
            float ax, ay;
            {
                float di = g_dinv[n];
                float c = di * di;
                float2 hv = h2[(size_t)n * 32 + lane];
                ax = hv.x * c;
                ay = hv.y * c;
            }
            int e = g_rowptr[n], end = g_rowptr[n + 1];
            for (; e + 4 <= end; e += 4) {
                unsigned long long p0 = g_edge[e];
                unsigned long long p1 = g_edge[e + 1];
                unsigned long long p2 = g_edge[e + 2];
                unsigned long long p3 = g_edge[e + 3];
                int i0 = (int)(unsigned)p0; float c0 = __uint_as_float((unsigned)(p0 >> 32));
                int i1 = (int)(unsigned)p1; float c1 = __uint_as_float((unsigned)(p1 >> 32));
                int i2 = (int)(unsigned)p2; float c2 = __uint_as_float((unsigned)(p2 >> 32));
                int i3 = (int)(unsigned)p3; float c3 = __uint_as_float((unsigned)(p3 >> 32));
                float2 v0 = h2[(size_t)i0 * 32 + lane];
                float2 v1 = h2[(size_t)i1 * 32 + lane];
                float2 v2 = h2[(size_t)i2 * 32 + lane];
                float2 v3 = h2[(size_t)i3 * 32 + lane];
                ax += v0.x * c0; ay += v0.y * c0;
                ax += v1.x * c1; ay += v1.y * c1;
                ax += v2.x * c2; ay += v2.y * c2;
                ax += v3.x * c3; ay += v3.y * c3;
            }
            for (; e < end; e++) {
                unsigned long long p = g_edge[e];
                int s = (int)(unsigned)p;
                float c = __uint_as_float((unsigned)(p >> 32));
                float2 hv = h2[(size_t)s * 32 + lane];
                ax += hv.x * c;
                ay += hv.y * c;
            }
            ax = fmaxf(ax, 0.f);
            ay = fmaxf(ay, 0.f);
            ((float2*)out)[(size_t)n * 32 + lane] = make_float2(ax, ay);
            s0 += ax; s1 += ay;
            q0 += ax * ax; q1 += ay * ay;
        }
        sm.agg.psum[warp][2 * lane]     = s0;
        sm.agg.psum[warp][2 * lane + 1] = s1;
        sm.agg.psq[warp][2 * lane]      = q0;
        sm.agg.psq[warp][2 * lane + 1]  = q1;
        __syncthreads();
        if (tid < F_OUT) {
            float a = 0.f, b = 0.f;
            #pragma unroll
            for (int w = 0; w < 32; w++) {
                a += sm.agg.psum[w][tid];
                b += sm.agg.psq[w][tid];
            }
            atomicAdd(&g_sum[tid], a);
            atomicAdd(&g_sumsq[tid], b);
        }
    }
    grid_sync(5);

    // ---------- Phase G: BN apply ----------
    {
        if (tid < F_OUT) {
            float invN = 1.0f / (float)N_NODES;
            float mean = g_sum[tid] * invN;
            float var = g_sumsq[tid] * invN - mean * mean;
            float sc = gamma[tid] * rsqrtf(var + BN_EPS);
            sm.bn.scale[tid] = sc;
            sm.bn.shift[tid] = beta[tid] - mean * sc;
        }
        __syncthreads();
        for (int i = gtid; i < N_NODES * F_OUT / 4; i += NTHREADS) {
            int f4 = (i & 15) * 4;
            float4 vv = ((float4*)out)[i];
            vv.x = vv.x * sm.bn.scale[f4 + 0] + sm.bn.shift[f4 + 0];
            vv.y = vv.y * sm.bn.scale[f4 + 1] + sm.bn.shift[f4 + 1];
            vv.z = vv.z * sm.bn.scale[f4 + 2] + sm.bn.shift[f4 + 2];
            vv.w = vv.w * sm.bn.scale[f4 + 3] + sm.bn.shift[f4 + 3];
            ((float4*)out)[i] = vv;
        }
    }
}

// ---------------- launch ----------------
extern "C" void kernel_launch(void* const* d_in, const int* in_sizes, int n_in,
                              void* d_out, int out_size) {
    const float* x     = (const float*)d_in[0];
    const int*   ei    = (const int*)d_in[1];     // int32 (JAX x64 disabled)
    const float* ew    = (const float*)d_in[2];
    const float* W     = (const float*)d_in[3];
    const float* gamma = (const float*)d_in[4];
    const float* beta  = (const float*)d_in[5];
    float*       out   = (float*)d_out;

    k_mega<<<NB, NT>>>(x, ei, ew, W, gamma, beta, out);
}

// round 7
// speedup vs baseline: 1.1393x; 1.1393x over previous
#include <cuda_runtime.h>
#include <cuda_bf16.h>

#define N_NODES 100000
#define N_EDGES 1600000
#define F_IN 128
#define F_OUT 64
#define BN_EPS 1e-5f

#define NB 148
#define NT 1024
#define HALF 512
#define NTHREADS (NB*NT)
#define EHALF (NB*HALF)
#define NODES_PER_BLK 676          // 148*676 = 100048
#define TILE_NODES 128
#define N_TILES 782                // 782*128 = 100096
#define KC 32
#define SXS 36

// ---------------- device scratch ----------------
__device__ __align__(16) float g_h[N_NODES * F_OUT];
__device__ __align__(16) float g_dinv[N_NODES];
__device__ int   g_deg[N_NODES];
__device__ int   g_cnt[N_NODES];
__device__ int   g_rowptr[N_NODES + 1];
__device__ int   g_cursor[N_NODES];
__device__ __align__(16) unsigned long long g_edge[N_EDGES];
__device__ int   g_bsum[NB];
__device__ float g_sum[F_OUT];
__device__ float g_sumsq[F_OUT];
__device__ int   g_wq;

struct Bar { int cnt; int flag; };
__device__ Bar g_bars[8];   // zero-init; self-resetting

__device__ __forceinline__ void barG() { asm volatile("bar.sync 1, 512;" ::: "memory"); }
__device__ __forceinline__ void barE() { asm volatile("bar.sync 2, 512;" ::: "memory"); }

__device__ __forceinline__ void bar_core(int i) {
    Bar* b = &g_bars[i];
    int snap = atomicAdd(&b->flag, 0);
    __threadfence();
    int old = atomicAdd(&b->cnt, 1);
    if (old == NB - 1) {
        atomicExch(&b->cnt, 0);
        __threadfence();
        atomicAdd(&b->flag, 1);
    } else {
        while (atomicAdd(&b->flag, 0) == snap) __nanosleep(64);
    }
    __threadfence();
}

__device__ __forceinline__ void grid_sync(int i) {       // all 1024 threads
    __syncthreads();
    if (threadIdx.x == 0) bar_core(i);
    __syncthreads();
}

__device__ __forceinline__ void edge_grid_sync(int i) {  // edge half only
    barE();
    if (threadIdx.x == HALF) bar_core(i);
    barE();
}

union SMemU {
    struct {
        float sW[KC * F_OUT];            // 8 KB   (gemm half)
        float sX[TILE_NODES * SXS];      // 18 KB  (gemm half)
        int   scan[HALF];                // 2 KB   (edge half)
        int   base;
    } p1;
    struct { float psum[32][F_OUT]; float psq[32][F_OUT]; } agg;   // 32 KB
    struct { float scale[F_OUT]; float shift[F_OUT]; } bn;
};

// scatter with work-stealing (both halves join)
__device__ __forceinline__ void scatter_steal(const int* __restrict__ ei,
                                              const float* __restrict__ ew,
                                              int lane) {
    for (;;) {
        int base = 0;
        if (lane == 0) base = atomicAdd(&g_wq, 256);
        base = __shfl_sync(0xffffffffu, base, 0);
        if (base >= N_EDGES) break;
        int lim = min(base + 256, N_EDGES);
        for (int e = base + lane; e < lim; e += 32) {
            int s = ei[e];
            int d = ei[N_EDGES + e];
            float c = g_dinv[s] * ew[e] * g_dinv[d];
            int p = atomicAdd(&g_cursor[d], 1);
            g_edge[p] = ((unsigned long long)__float_as_uint(c) << 32) | (unsigned)s;
        }
    }
}

__global__ __launch_bounds__(NT, 1)
void k_mega(const float* __restrict__ x, const int* __restrict__ ei,
            const float* __restrict__ ew, const float* __restrict__ W,
            const float* __restrict__ gamma, const float* __restrict__ beta,
            float* __restrict__ out) {
    __shared__ SMemU sm;
    int tid = threadIdx.x;
    int bid = blockIdx.x;
    int gtid = bid * NT + tid;
    int lane = tid & 31;

    // snapshot of edge-barrier-3 flag, taken BEFORE our arrival at sync0
    // (bar3 of this replay cannot release before all blocks pass sync0)
    int snap3 = 0;
    if (tid < HALF && lane == 0) snap3 = atomicAdd(&g_bars[3].flag, 0);

    // ---------- init ----------
    for (int i = gtid; i < N_NODES; i += NTHREADS) { g_deg[i] = 1; g_cnt[i] = 0; }
    if (gtid < F_OUT) { g_sum[gtid] = 0.f; g_sumsq[gtid] = 0.f; }
    if (gtid == 0) { g_rowptr[N_NODES] = N_EDGES; g_wq = 0; }
    grid_sync(0);

    if (tid < HALF) {
        // ================= GEMM half (warps 0-15) =================
        int og = tid & 15;       // 16 out-groups x 4 outs
        int ng = tid >> 4;       // 32 node-groups x 4 nodes
        for (int tile = bid; tile < N_TILES; tile += NB) {
            int nbase = tile * TILE_NODES;
            unsigned long long acc[4][2];
            #pragma unroll
            for (int a = 0; a < 4; a++) { acc[a][0] = 0ull; acc[a][1] = 0ull; }

            for (int kc = 0; kc < F_IN; kc += KC) {
                barG();
                // sW chunk: transpose W[o][kc..kc+31] -> sW[k][o], conflict-free STS
                {
                    int o = tid & 63, kq = tid >> 6;   // kq 0..7
                    float4 wv = *(const float4*)&W[o * F_IN + kc + kq * 4];
                    sm.p1.sW[(kq * 4 + 0) * F_OUT + o] = wv.x;
                    sm.p1.sW[(kq * 4 + 1) * F_OUT + o] = wv.y;
                    sm.p1.sW[(kq * 4 + 2) * F_OUT + o] = wv.z;
                    sm.p1.sW[(kq * 4 + 3) * F_OUT + o] = wv.w;
                }
                // sX chunk: 128 nodes x KC
                #pragma unroll
                for (int i = tid; i < TILE_NODES * (KC / 4); i += HALF) {
                    int n = i >> 3, kq = i & 7;
                    int gn = nbase + n;
                    float4 val = make_float4(0.f, 0.f, 0.f, 0.f);
                    if (gn < N_NODES)
                        val = *(const float4*)&x[(size_t)gn * F_IN + kc + kq * 4];
                    *(float4*)&sm.p1.sX[n * SXS + kq * 4] = val;
                }
                barG();

                #pragma unroll 4
                for (int kp = 0; kp < KC; kp += 2) {
                    ulonglong2 wA = *(const ulonglong2*)&sm.p1.sW[kp * F_OUT + og * 4];
                    ulonglong2 wB = *(const ulonglong2*)&sm.p1.sW[(kp + 1) * F_OUT + og * 4];
                    #pragma unroll
                    for (int ni = 0; ni < 4; ni++) {
                        float2 xv = *(const float2*)&sm.p1.sX[(ng * 4 + ni) * SXS + kp];
                        unsigned long long x0d, x1d;
                        unsigned x0 = __float_as_uint(xv.x);
                        unsigned x1 = __float_as_uint(xv.y);
                        asm("mov.b64 %0, {%1, %1};" : "=l"(x0d) : "r"(x0));
                        asm("mov.b64 %0, {%1, %1};" : "=l"(x1d) : "r"(x1));
                        asm("fma.rn.f32x2 %0, %1, %2, %0;" : "+l"(acc[ni][0]) : "l"(wA.x), "l"(x0d));
                        asm("fma.rn.f32x2 %0, %1, %2, %0;" : "+l"(acc[ni][1]) : "l"(wA.y), "l"(x0d));
                        asm("fma.rn.f32x2 %0, %1, %2, %0;" : "+l"(acc[ni][0]) : "l"(wB.x), "l"(x1d));
                        asm("fma.rn.f32x2 %0, %1, %2, %0;" : "+l"(acc[ni][1]) : "l"(wB.y), "l"(x1d));
                    }
                }
            }
            #pragma unroll
            for (int ni = 0; ni < 4; ni++) {
                int n = nbase + ng * 4 + ni;
                if (n < N_NODES) {
                    unsigned a0, a1, a2, a3;
                    asm("mov.b64 {%0, %1}, %2;" : "=r"(a0), "=r"(a1) : "l"(acc[ni][0]));
                    asm("mov.b64 {%0, %1}, %2;" : "=r"(a2), "=r"(a3) : "l"(acc[ni][1]));
                    *(float4*)&g_h[(size_t)n * F_OUT + og * 4] =
                        make_float4(__uint_as_float(a0), __uint_as_float(a1),
                                    __uint_as_float(a2), __uint_as_float(a3));
                }
            }
        }
        // wait for edge pipeline's CSR setup (bar3), then help scatter
        if (lane == 0) {
            while (atomicAdd(&g_bars[3].flag, 0) == snap3) __nanosleep(128);
        }
        __syncwarp();
        __threadfence();
        scatter_steal(ei, ew, lane);
    } else {
        // ================= edge half (warps 16-31) =================
        int et = tid - HALF;                 // 0..511
        // degree + dst histogram
        for (int e = bid * HALF + et; e < N_EDGES; e += EHALF) {
            int s = ei[e];
            int d = ei[N_EDGES + e];
            atomicAdd(&g_deg[s], 1);
            atomicAdd(&g_cnt[d], 1);
        }
        edge_grid_sync(1);

        // dinv + block-local scan (2 nodes per thread)
        int nb0 = bid * NODES_PER_BLK + 2 * et;
        int v0 = 0, v1 = 0;
        if (et < NODES_PER_BLK / 2) {
            if (nb0 < N_NODES) { v0 = g_cnt[nb0]; g_dinv[nb0] = rsqrtf((float)g_deg[nb0]); }
            if (nb0 + 1 < N_NODES) { v1 = g_cnt[nb0 + 1]; g_dinv[nb0 + 1] = rsqrtf((float)g_deg[nb0 + 1]); }
        }
        int pair = v0 + v1;
        sm.p1.scan[et] = pair;
        barE();
        for (int off = 1; off < HALF; off <<= 1) {
            int t = (et >= off) ? sm.p1.scan[et - off] : 0;
            barE();
            sm.p1.scan[et] += t;
            barE();
        }
        int incl = sm.p1.scan[et];
        if (et == HALF - 1) g_bsum[bid] = incl;
        edge_grid_sync(2);

        // block base = sum of previous block totals
        if (et < 32) {
            int acc = 0;
            for (int j = et; j < bid; j += 32) acc += g_bsum[j];
            #pragma unroll
            for (int off = 16; off > 0; off >>= 1)
                acc += __shfl_xor_sync(0xffffffffu, acc, off);
            if (et == 0) sm.p1.base = acc;
        }
        barE();
        if (et < NODES_PER_BLK / 2) {
            int e1 = sm.p1.base + incl - pair;    // exclusive for nb0
            if (nb0 < N_NODES) { g_rowptr[nb0] = e1; g_cursor[nb0] = e1; }
            int e2 = e1 + v0;
            if (nb0 + 1 < N_NODES) { g_rowptr[nb0 + 1] = e2; g_cursor[nb0 + 1] = e2; }
        }
        edge_grid_sync(3);
        scatter_steal(ei, ew, lane);
    }

    grid_sync(4);

    // ---------- aggregation (all 32 warps) + BN partial sums ----------
    {
        int warp = tid >> 5;
        float s0 = 0.f, s1 = 0.f, q0 = 0.f, q1 = 0.f;
        const float2* h2 = (const float2*)g_h;
        for (int n = bid * 32 + warp; n < N_NODES; n += NB * 32) {
            float ax, ay;
            {
                float di = g_dinv[n];
                float c = di * di;
                float2 hv = h2[(size_t)n * 32 + lane];
                ax = hv.x * c;
                ay = hv.y * c;
            }
            int e = g_rowptr[n], end = g_rowptr[n + 1];
            for (; e + 4 <= end; e += 4) {
                unsigned long long p0 = g_edge[e];
                unsigned long long p1 = g_edge[e + 1];
                unsigned long long p2 = g_edge[e + 2];
                unsigned long long p3 = g_edge[e + 3];
                int i0 = (int)(unsigned)p0; float c0 = __uint_as_float((unsigned)(p0 >> 32));
                int i1 = (int)(unsigned)p1; float c1 = __uint_as_float((unsigned)(p1 >> 32));
                int i2 = (int)(unsigned)p2; float c2 = __uint_as_float((unsigned)(p2 >> 32));
                int i3 = (int)(unsigned)p3; float c3 = __uint_as_float((unsigned)(p3 >> 32));
                float2 u0 = h2[(size_t)i0 * 32 + lane];
                float2 u1 = h2[(size_t)i1 * 32 + lane];
                float2 u2 = h2[(size_t)i2 * 32 + lane];
                float2 u3 = h2[(size_t)i3 * 32 + lane];
                ax += u0.x * c0; ay += u0.y * c0;
                ax += u1.x * c1; ay += u1.y * c1;
                ax += u2.x * c2; ay += u2.y * c2;
                ax += u3.x * c3; ay += u3.y * c3;
            }
            for (; e < end; e++) {
                unsigned long long p = g_edge[e];
                int s = (int)(unsigned)p;
                float c = __uint_as_float((unsigned)(p >> 32));
                float2 hv = h2[(size_t)s * 32 + lane];
                ax += hv.x * c;
                ay += hv.y * c;
            }
            ax = fmaxf(ax, 0.f);
            ay = fmaxf(ay, 0.f);
            ((float2*)out)[(size_t)n * 32 + lane] = make_float2(ax, ay);
            s0 += ax; s1 += ay;
            q0 += ax * ax; q1 += ay * ay;
        }
        sm.agg.psum[warp][2 * lane]     = s0;
        sm.agg.psum[warp][2 * lane + 1] = s1;
        sm.agg.psq[warp][2 * lane]      = q0;
        sm.agg.psq[warp][2 * lane + 1]  = q1;
        __syncthreads();
        if (tid < F_OUT) {
            float a = 0.f, b = 0.f;
            #pragma unroll
            for (int w = 0; w < 32; w++) {
                a += sm.agg.psum[w][tid];
                b += sm.agg.psq[w][tid];
            }
            atomicAdd(&g_sum[tid], a);
            atomicAdd(&g_sumsq[tid], b);
        }
    }
    grid_sync(5);

    // ---------- BN apply ----------
    {
        if (tid < F_OUT) {
            float invN = 1.0f / (float)N_NODES;
            float mean = g_sum[tid] * invN;
            float var = g_sumsq[tid] * invN - mean * mean;
            float sc = gamma[tid] * rsqrtf(var + BN_EPS);
            sm.bn.scale[tid] = sc;
            sm.bn.shift[tid] = beta[tid] - mean * sc;
        }
        __syncthreads();
        for (int i = gtid; i < N_NODES * F_OUT / 4; i += NTHREADS) {
            int f4 = (i & 15) * 4;
            float4 vv = ((float4*)out)[i];
            vv.x = vv.x * sm.bn.scale[f4 + 0] + sm.bn.shift[f4 + 0];
            vv.y = vv.y * sm.bn.scale[f4 + 1] + sm.bn.shift[f4 + 1];
            vv.z = vv.z * sm.bn.scale[f4 + 2] + sm.bn.shift[f4 + 2];
            vv.w = vv.w * sm.bn.scale[f4 + 3] + sm.bn.shift[f4 + 3];
            ((float4*)out)[i] = vv;
        }
    }
}

// ---------------- launch ----------------
extern "C" void kernel_launch(void* const* d_in, const int* in_sizes, int n_in,
                              void* d_out, int out_size) {
    const float* x     = (const float*)d_in[0];
    const int*   ei    = (const int*)d_in[1];     // int32 (JAX x64 disabled)
    const float* ew    = (const float*)d_in[2];
    const float* W     = (const float*)d_in[3];
    const float* gamma = (const float*)d_in[4];
    const float* beta  = (const float*)d_in[5];
    float*       out   = (float*)d_out;

    k_mega<<<NB, NT>>>(x, ei, ew, W, gamma, beta, out);
}